// round 6
// baseline (speedup 1.0000x reference)
#include <cuda_runtime.h>

// FFM forward: B=16384, F=6 fields, LATENT=16.
// Pure random-gather workload; one block per sample, coalesced 64B row reads.

#define NF      6
#define LATENT  16
#define TOTIDX  74   // sum of SEQ

struct FfmParams {
    const int*   x[NF];
    const float* E[NF];   // (F-1, DIMS[i], LATENT) row-major
    const float* L[NF];   // (DIMS[i], 1)
    const float* Wd;      // (F, 1)
    const float* bd;      // (1,)
    float*       out;     // (B, 1)
};

__global__ __launch_bounds__(96) void ffm_kernel(FfmParams p) {
    // Shape constants live INSIDE the kernel so nvcc folds them to immediates.
    constexpr int       SEQ[NF]  = {1, 1, 50, 20, 1, 1};
    constexpr int       OFF[NF]  = {0, 1, 2, 52, 72, 73};   // prefix sums of SEQ
    constexpr long long DIMS[NF] = {1000000, 500000, 500000, 100000, 10000, 1000};

    const int b   = blockIdx.x;
    const int tid = threadIdx.x;

    __shared__ int   sidx[TOTIDX];
    __shared__ float v[NF][NF - 1][LATENT];   // mean-pooled pair embeddings
    __shared__ float lpart[NF][16];           // partial linear sums

    // ---- preload all indices for this sample ----
#pragma unroll
    for (int i = 0; i < NF; ++i) {
        if (tid < SEQ[i]) {
            sidx[OFF[i] + tid] = p.x[i][(long long)b * SEQ[i] + tid];
        }
    }
    __syncthreads();

    if (tid < 80) {
        // ---- embedding gather: thread = (slot, latent lane) ----
        const int slot = tid >> 4;    // 0..4
        const int l    = tid & 15;    // 0..15
#pragma unroll
        for (int i = 0; i < NF; ++i) {
            const float* base = p.E[i] + ((long long)slot * DIMS[i]) * LATENT + l;
            float acc = 0.0f;
#pragma unroll 8
            for (int s = 0; s < SEQ[i]; ++s) {
                acc += __ldg(base + (long long)sidx[OFF[i] + s] * LATENT);
            }
            v[i][slot][l] = acc * (1.0f / (float)SEQ[i]);
        }
    } else {
        // ---- linear-term gather (threads 80..95), strided partials ----
        const int t = tid - 80;       // 0..15
#pragma unroll
        for (int i = 0; i < NF; ++i) {
            float acc = 0.0f;
            for (int s = t; s < SEQ[i]; s += 16) {
                acc += __ldg(p.L[i] + sidx[OFF[i] + s]);
            }
            lpart[i][t] = acc;
        }
    }
    __syncthreads();

    // ---- FM interaction: fm = sum_{i<j} dot(v[i][j-1], v[j][i]) ----
    if (tid < 16) {
        float fmp = 0.0f;
#pragma unroll
        for (int i = 0; i < NF; ++i) {
#pragma unroll
            for (int j = i + 1; j < NF; ++j) {
                fmp += v[i][j - 1][tid] * v[j][i][tid];
            }
        }
#pragma unroll
        for (int off = 8; off > 0; off >>= 1) {
            fmp += __shfl_down_sync(0x0000FFFFu, fmp, off);
        }

        if (tid == 0) {
            float lin = __ldg(p.bd);
#pragma unroll
            for (int i = 0; i < NF; ++i) {
                float ls = 0.0f;
#pragma unroll
                for (int t = 0; t < 16; ++t) ls += lpart[i][t];
                lin += (ls * (1.0f / (float)SEQ[i])) * __ldg(p.Wd + i);
            }
            lin = fmaxf(lin, 0.0f);
            const float z = lin + fmp;
            p.out[b] = 1.0f / (1.0f + __expf(-z));
        }
    }
}

extern "C" void kernel_launch(void* const* d_in, const int* in_sizes, int n_in,
                              void* d_out, int out_size) {
    FfmParams p;
    for (int i = 0; i < NF; ++i) p.x[i] = (const int*)d_in[i];   // x0..x5

    // setup_inputs() interleaves E and L: order is E0,L0,E1,L1,...,E5,L5.
    // Auto-detect from element counts to be robust: L0 has 1e6 elems, E1 has 40e6.
    const bool interleaved = (in_sizes[7] < 2000000);
    for (int i = 0; i < NF; ++i) {
        if (interleaved) {
            p.E[i] = (const float*)d_in[6 + 2 * i];
            p.L[i] = (const float*)d_in[7 + 2 * i];
        } else {
            p.E[i] = (const float*)d_in[6 + i];
            p.L[i] = (const float*)d_in[12 + i];
        }
    }
    p.Wd  = (const float*)d_in[18];
    p.bd  = (const float*)d_in[19];
    p.out = (float*)d_out;

    const int B = in_sizes[0];                   // x0 is (B, 1)
    ffm_kernel<<<B, 96>>>(p);
}